// round 1
// baseline (speedup 1.0000x reference)
#include <cuda_runtime.h>
#include <math.h>

#define B 32
#define N 32768
#define D 128
#define C1 128
#define NCH1 (N / C1)   // 256
#define C3 128
#define NCH3 (N / C3)   // 256

// scratch (no allocations allowed)
__device__ float g_logits[B * N];        // 4 MB
__device__ float g_pmax[B * NCH1];
__device__ float g_gmax[B];
__device__ float g_psum[B * NCH3];
__device__ float g_pvec[NCH3 * B * D];   // 4 MB

// ---------------------------------------------------------------------------
// K1: logits[b][n] = A[b] + (sqrt(a)/var)*dot(x_b,y_n) - (0.5a/var)*||y_n||^2
// one thread per n, all 32 b accumulated in registers; x staged in smem.
// ---------------------------------------------------------------------------
__global__ __launch_bounds__(C1) void k_logits(const float* __restrict__ x,
                                               const float* __restrict__ al,
                                               const float* __restrict__ y) {
    __shared__ float xs[B * D];
    __shared__ float sA[B], sB[B], sC[B];
    __shared__ float wmax[B][4];
    const int t = threadIdx.x;

    for (int i = t; i < B * D; i += C1) xs[i] = x[i];
    if (t < B) {
        float a = al[t];
        float var = 1.0f - a;
        float x2 = 0.f;
        #pragma unroll 4
        for (int d = 0; d < D; d++) { float v = x[t * D + d]; x2 = fmaf(v, v, x2); }
        sA[t] = -(0.5f * (float)D * logf(var) + 0.5f / var * x2);
        sB[t] = sqrtf(a) / var;
        sC[t] = 0.5f * a / var;
    }
    __syncthreads();

    const int n = blockIdx.x * C1 + t;
    float dot[B];
    #pragma unroll
    for (int b = 0; b < B; b++) dot[b] = 0.f;
    float y2 = 0.f;

    const float4* y4 = reinterpret_cast<const float4*>(y) + n * (D / 4);
    const float4* xs4 = reinterpret_cast<const float4*>(xs);
    #pragma unroll 4
    for (int d4 = 0; d4 < D / 4; d4++) {
        float4 yv = y4[d4];
        y2 = fmaf(yv.x, yv.x, fmaf(yv.y, yv.y, fmaf(yv.z, yv.z, fmaf(yv.w, yv.w, y2))));
        #pragma unroll
        for (int b = 0; b < B; b++) {
            float4 xv = xs4[b * (D / 4) + d4];
            dot[b] = fmaf(xv.x, yv.x, dot[b]);
            dot[b] = fmaf(xv.y, yv.y, dot[b]);
            dot[b] = fmaf(xv.z, yv.z, dot[b]);
            dot[b] = fmaf(xv.w, yv.w, dot[b]);
        }
    }

    const int lane = t & 31, w = t >> 5;
    #pragma unroll
    for (int b = 0; b < B; b++) {
        float l = fmaf(sB[b], dot[b], sA[b]) - sC[b] * y2;
        g_logits[b * N + n] = l;
        float m = l;
        #pragma unroll
        for (int o = 16; o > 0; o >>= 1) m = fmaxf(m, __shfl_xor_sync(0xffffffffu, m, o));
        if (lane == 0) wmax[b][w] = m;
    }
    __syncthreads();
    if (t < B) {
        float m = fmaxf(fmaxf(wmax[t][0], wmax[t][1]), fmaxf(wmax[t][2], wmax[t][3]));
        g_pmax[t * NCH1 + blockIdx.x] = m;
    }
}

// ---------------------------------------------------------------------------
// K2: global row max. 32 warps, warp w reduces row w.
// ---------------------------------------------------------------------------
__global__ void k_gmax() {
    const int b = threadIdx.x >> 5, lane = threadIdx.x & 31;
    float m = -INFINITY;
    for (int c = lane; c < NCH1; c += 32) m = fmaxf(m, g_pmax[b * NCH1 + c]);
    #pragma unroll
    for (int o = 16; o > 0; o >>= 1) m = fmaxf(m, __shfl_xor_sync(0xffffffffu, m, o));
    if (lane == 0) g_gmax[b] = m;
}

// ---------------------------------------------------------------------------
// K3: e = exp(logit - gmax); partial sum_e per (b,chunk); partial
// vec[b][d] += e * y[n][d] per chunk. Thread owns d; e staged in smem.
// ---------------------------------------------------------------------------
__global__ __launch_bounds__(128) void k_accum(const float* __restrict__ y) {
    __shared__ float es[B][C3];   // 16 KB, rows 512B -> float4 aligned
    __shared__ float gm[B];
    const int t = threadIdx.x;
    const int base = blockIdx.x * C3;

    if (t < B) gm[t] = g_gmax[t];
    __syncthreads();

    #pragma unroll
    for (int k = 0; k < B; k++) {
        float l = g_logits[k * N + base + t];
        es[k][t] = __expf(l - gm[k]);
    }
    __syncthreads();

    // partial sum_e per b (warp w handles b = w, w+4, ...)
    const int w = t >> 5, lane = t & 31;
    #pragma unroll
    for (int j = 0; j < B / 4; j++) {
        int b = w * (B / 4) + j;
        float s = es[b][lane] + es[b][lane + 32] + es[b][lane + 64] + es[b][lane + 96];
        #pragma unroll
        for (int o = 16; o > 0; o >>= 1) s += __shfl_xor_sync(0xffffffffu, s, o);
        if (lane == 0) g_psum[b * NCH3 + blockIdx.x] = s;
    }

    float acc[B];
    #pragma unroll
    for (int b = 0; b < B; b++) acc[b] = 0.f;

    #pragma unroll 2
    for (int n4 = 0; n4 < C3 / 4; n4++) {
        const int n = n4 * 4;
        float y0 = y[(size_t)(base + n + 0) * D + t];
        float y1 = y[(size_t)(base + n + 1) * D + t];
        float y2v = y[(size_t)(base + n + 2) * D + t];
        float y3 = y[(size_t)(base + n + 3) * D + t];
        #pragma unroll
        for (int b = 0; b < B; b++) {
            float4 e = *reinterpret_cast<const float4*>(&es[b][n]);
            acc[b] = fmaf(e.x, y0, acc[b]);
            acc[b] = fmaf(e.y, y1, acc[b]);
            acc[b] = fmaf(e.z, y2v, acc[b]);
            acc[b] = fmaf(e.w, y3, acc[b]);
        }
    }

    float* pv = g_pvec + (size_t)blockIdx.x * B * D;
    #pragma unroll
    for (int b = 0; b < B; b++) pv[b * D + t] = acc[b];
}

// ---------------------------------------------------------------------------
// K4: final reduce over chunks + epilogue. block b, thread d.
// ---------------------------------------------------------------------------
__global__ __launch_bounds__(D) void k_final(const float* __restrict__ x,
                                             const float* __restrict__ al,
                                             float* __restrict__ out) {
    const int b = blockIdx.x, t = threadIdx.x;
    float se = 0.f;
    #pragma unroll 4
    for (int c = 0; c < NCH3; c++) se += g_psum[b * NCH3 + c];
    float v = 0.f;
    #pragma unroll 4
    for (int c = 0; c < NCH3; c++) v += g_pvec[(size_t)c * B * D + b * D + t];
    float a = al[b];
    float var = 1.f - a;
    float x0 = v / se;
    out[b * D + t] = (x[b * D + t] - sqrtf(a) * x0) * rsqrtf(var);
}

extern "C" void kernel_launch(void* const* d_in, const int* in_sizes, int n_in,
                              void* d_out, int out_size) {
    const float* x  = (const float*)d_in[0];   // inputs [B, D]
    const float* al = (const float*)d_in[1];   // alphas [B]
    const float* y  = (const float*)d_in[2];   // data_batch [N, D]
    float* out = (float*)d_out;                // [B, D]

    k_logits<<<NCH1, C1>>>(x, al, y);
    k_gmax<<<1, 1024>>>();
    k_accum<<<NCH3, 128>>>(y);
    k_final<<<B, D>>>(x, al, out);
}

// round 2
// speedup vs baseline: 1.4211x; 1.4211x over previous
#include <cuda_runtime.h>
#include <math.h>

#define B 32
#define N 32768
#define D 128
#define C1 256
#define NCH1 (N / C1)   // 128 blocks for k_logits
#define C3 128
#define NCH3 (N / C3)   // 256 chunks for k_accum

// scratch (no allocations allowed)
__device__ float g_logits[B * N];        // 4 MB
__device__ float g_pmax[B * NCH1];
__device__ float g_gmax[B];
__device__ float g_psum[B * NCH3];
__device__ float g_se[B];
__device__ float g_pvec[NCH3 * B * D];   // 4 MB

// ---------------------------------------------------------------------------
// K1: logits[b][n] = A[b] + (sqrt(a)/var)*dot(x_b,y_n) - (0.5a/var)*||y_n||^2
// one thread per n, all 32 b accumulated in registers; x staged in smem.
// ---------------------------------------------------------------------------
__global__ __launch_bounds__(C1) void k_logits(const float* __restrict__ x,
                                               const float* __restrict__ al,
                                               const float* __restrict__ y) {
    __shared__ float xs[B * D];
    __shared__ float sA[B], sB[B], sC[B];
    __shared__ float wmax[B][C1 / 32];
    const int t = threadIdx.x;

    for (int i = t; i < B * D; i += C1) xs[i] = x[i];
    if (t < B) {
        float a = al[t];
        float var = 1.0f - a;
        float x2 = 0.f;
        #pragma unroll 4
        for (int d = 0; d < D; d++) { float v = x[t * D + d]; x2 = fmaf(v, v, x2); }
        sA[t] = -(0.5f * (float)D * logf(var) + 0.5f / var * x2);
        sB[t] = sqrtf(a) / var;
        sC[t] = 0.5f * a / var;
    }
    __syncthreads();

    const int n = blockIdx.x * C1 + t;
    float dot[B];
    #pragma unroll
    for (int b = 0; b < B; b++) dot[b] = 0.f;
    float y2 = 0.f;

    const float4* y4 = reinterpret_cast<const float4*>(y) + n * (D / 4);
    const float4* xs4 = reinterpret_cast<const float4*>(xs);
    #pragma unroll 4
    for (int d4 = 0; d4 < D / 4; d4++) {
        float4 yv = y4[d4];
        y2 = fmaf(yv.x, yv.x, fmaf(yv.y, yv.y, fmaf(yv.z, yv.z, fmaf(yv.w, yv.w, y2))));
        #pragma unroll
        for (int b = 0; b < B; b++) {
            float4 xv = xs4[b * (D / 4) + d4];
            dot[b] = fmaf(xv.x, yv.x, dot[b]);
            dot[b] = fmaf(xv.y, yv.y, dot[b]);
            dot[b] = fmaf(xv.z, yv.z, dot[b]);
            dot[b] = fmaf(xv.w, yv.w, dot[b]);
        }
    }

    const int lane = t & 31, w = t >> 5;
    #pragma unroll
    for (int b = 0; b < B; b++) {
        float l = fmaf(sB[b], dot[b], sA[b]) - sC[b] * y2;
        g_logits[b * N + n] = l;
        float m = l;
        #pragma unroll
        for (int o = 16; o > 0; o >>= 1) m = fmaxf(m, __shfl_xor_sync(0xffffffffu, m, o));
        if (lane == 0) wmax[b][w] = m;
    }
    __syncthreads();
    if (t < B) {
        float m = -INFINITY;
        #pragma unroll
        for (int w2 = 0; w2 < C1 / 32; w2++) m = fmaxf(m, wmax[t][w2]);
        g_pmax[t * NCH1 + blockIdx.x] = m;
    }
}

// ---------------------------------------------------------------------------
// K2: global row max. 32 warps, warp w reduces row w.
// ---------------------------------------------------------------------------
__global__ void k_gmax() {
    const int b = threadIdx.x >> 5, lane = threadIdx.x & 31;
    float m = -INFINITY;
    #pragma unroll
    for (int c = lane; c < NCH1; c += 32) m = fmaxf(m, g_pmax[b * NCH1 + c]);
    #pragma unroll
    for (int o = 16; o > 0; o >>= 1) m = fmaxf(m, __shfl_xor_sync(0xffffffffu, m, o));
    if (lane == 0) g_gmax[b] = m;
}

// ---------------------------------------------------------------------------
// K3: e = exp(logit - gmax); partial sum_e per (b,chunk); partial
// vec[b][d] += e * y[n][d] per chunk. Thread owns d; e staged in smem.
// ---------------------------------------------------------------------------
__global__ __launch_bounds__(128) void k_accum(const float* __restrict__ y) {
    __shared__ float es[B][C3];   // 16 KB
    __shared__ float gm[B];
    const int t = threadIdx.x;
    const int base = blockIdx.x * C3;

    if (t < B) gm[t] = g_gmax[t];
    __syncthreads();

    #pragma unroll
    for (int k = 0; k < B; k++) {
        float l = g_logits[k * N + base + t];
        es[k][t] = __expf(l - gm[k]);
    }
    __syncthreads();

    // partial sum_e per b (warp w handles 8 consecutive b)
    const int w = t >> 5, lane = t & 31;
    #pragma unroll
    for (int j = 0; j < B / 4; j++) {
        int b = w * (B / 4) + j;
        float s = es[b][lane] + es[b][lane + 32] + es[b][lane + 64] + es[b][lane + 96];
        #pragma unroll
        for (int o = 16; o > 0; o >>= 1) s += __shfl_xor_sync(0xffffffffu, s, o);
        if (lane == 0) g_psum[b * NCH3 + blockIdx.x] = s;
    }

    float acc[B];
    #pragma unroll
    for (int b = 0; b < B; b++) acc[b] = 0.f;

    #pragma unroll 2
    for (int n4 = 0; n4 < C3 / 4; n4++) {
        const int n = n4 * 4;
        float y0 = y[(size_t)(base + n + 0) * D + t];
        float y1 = y[(size_t)(base + n + 1) * D + t];
        float y2v = y[(size_t)(base + n + 2) * D + t];
        float y3 = y[(size_t)(base + n + 3) * D + t];
        #pragma unroll
        for (int b = 0; b < B; b++) {
            float4 e = *reinterpret_cast<const float4*>(&es[b][n]);
            acc[b] = fmaf(e.x, y0, acc[b]);
            acc[b] = fmaf(e.y, y1, acc[b]);
            acc[b] = fmaf(e.z, y2v, acc[b]);
            acc[b] = fmaf(e.w, y3, acc[b]);
        }
    }

    float* pv = g_pvec + (size_t)blockIdx.x * B * D;
    #pragma unroll
    for (int b = 0; b < B; b++) pv[b * D + t] = acc[b];
}

// ---------------------------------------------------------------------------
// K4: sum_e[b] = sum over chunks of psum. 1 block, warp b reduces row b.
// ---------------------------------------------------------------------------
__global__ void k_sum() {
    const int b = threadIdx.x >> 5, lane = threadIdx.x & 31;
    float s = 0.f;
    #pragma unroll
    for (int c = lane; c < NCH3; c += 32) s += g_psum[b * NCH3 + c];
    #pragma unroll
    for (int o = 16; o > 0; o >>= 1) s += __shfl_xor_sync(0xffffffffu, s, o);
    if (lane == 0) g_se[b] = s;
}

// ---------------------------------------------------------------------------
// K5: warp-per-output reduction over chunk partials + epilogue.
// 4096 outputs (b,d); global warp w owns one; lane strides chunks.
// ---------------------------------------------------------------------------
__global__ __launch_bounds__(128) void k_reduce(const float* __restrict__ x,
                                                const float* __restrict__ al,
                                                float* __restrict__ out) {
    const int t = threadIdx.x;
    const int lane = t & 31;
    const int w = blockIdx.x * 4 + (t >> 5);  // 0..4095
    const int b = w >> 7;                     // / D
    const int d = w & (D - 1);

    float v = 0.f;
    #pragma unroll
    for (int j = 0; j < NCH3 / 32; j++) {
        int c = j * 32 + lane;
        v += g_pvec[(size_t)c * B * D + b * D + d];
    }
    #pragma unroll
    for (int o = 16; o > 0; o >>= 1) v += __shfl_xor_sync(0xffffffffu, v, o);

    if (lane == 0) {
        float se = g_se[b];
        float a = al[b];
        float var = 1.f - a;
        out[b * D + d] = (x[b * D + d] - sqrtf(a) * (v / se)) * rsqrtf(var);
    }
}

extern "C" void kernel_launch(void* const* d_in, const int* in_sizes, int n_in,
                              void* d_out, int out_size) {
    const float* x  = (const float*)d_in[0];   // inputs [B, D]
    const float* al = (const float*)d_in[1];   // alphas [B]
    const float* y  = (const float*)d_in[2];   // data_batch [N, D]
    float* out = (float*)d_out;                // [B, D]

    k_logits<<<NCH1, C1>>>(x, al, y);
    k_gmax<<<1, 1024>>>();
    k_accum<<<NCH3, 128>>>(y);
    k_sum<<<1, 1024>>>();
    k_reduce<<<B * D / 4, 128>>>(x, al, out);
}

// round 3
// speedup vs baseline: 1.6647x; 1.1714x over previous
#include <cuda_runtime.h>
#include <math.h>

#define B 32
#define N 32768
#define D 128
#define CH 128
#define NCH (N / CH)          // 256 chunks
#define YSTRIDE (D + 4)       // 132 floats: pad to kill LDS.128 bank conflicts

// per-chunk softmax partials (no allocations allowed)
__device__ float g_cmax[B * NCH];        // [B][NCH]
__device__ float g_csum[B * NCH];        // [B][NCH]
__device__ float g_cvec[NCH * B * D];    // [NCH][B][D], 4 MB

// ---------------------------------------------------------------------------
// K1: fused chunk kernel. One CTA per 128-n chunk, 128 threads.
//  Phase A: thread t owns n=base+t; dot(x_b, y_n) for all 32 b (y,x in smem)
//           -> logits -> chunk max per b -> e = exp(l - cmax) -> chunk sum.
//  Phase B: thread t owns d=t; acc[b] = sum_n e[b][n] * y[n][d].
//  y is read from DRAM exactly once, staged in padded smem.
// ---------------------------------------------------------------------------
__global__ __launch_bounds__(128) void k_chunk(const float* __restrict__ x,
                                               const float* __restrict__ al,
                                               const float* __restrict__ y) {
    extern __shared__ float smem[];
    float* ys = smem;                    // CH * YSTRIDE   (67.6 KB)
    float* xs = ys + CH * YSTRIDE;       // B * D          (16 KB)
    float* es = xs + B * D;              // B * CH         (16 KB) logits->exp
    __shared__ float sA[B], sScale[B], sC[B], cm[B];
    __shared__ float wred[B][4];

    const int t = threadIdx.x;
    const int base = blockIdx.x * CH;

    // stage y chunk (coalesced float4, padded rows)
    const float4* y4 = reinterpret_cast<const float4*>(y + (size_t)base * D);
    #pragma unroll
    for (int i = t; i < CH * D / 4; i += 128) {
        int row = i >> 5;               // i / (D/4)
        int c4  = i & 31;
        *reinterpret_cast<float4*>(&ys[row * YSTRIDE + c4 * 4]) = y4[i];
    }
    // stage x
    const float4* x4 = reinterpret_cast<const float4*>(x);
    #pragma unroll
    for (int i = t; i < B * D / 4; i += 128)
        reinterpret_cast<float4*>(xs)[i] = x4[i];
    __syncthreads();

    if (t < B) {
        float a = al[t];
        float var = 1.0f - a;
        float x2 = 0.f;
        #pragma unroll 8
        for (int d = 0; d < D; d++) { float v = xs[t * D + d]; x2 = fmaf(v, v, x2); }
        sA[t] = -(0.5f * (float)D * logf(var) + 0.5f / var * x2);
        sScale[t] = sqrtf(a) / var;
        sC[t] = 0.5f * a / var;
    }
    __syncthreads();

    // ---- Phase A: dots + logits ----
    float dot[B];
    #pragma unroll
    for (int b = 0; b < B; b++) dot[b] = 0.f;
    float y2 = 0.f;

    const float4* yrow = reinterpret_cast<const float4*>(&ys[t * YSTRIDE]);
    const float4* xs4  = reinterpret_cast<const float4*>(xs);
    #pragma unroll 4
    for (int d4 = 0; d4 < D / 4; d4++) {
        float4 yv = yrow[d4];
        y2 = fmaf(yv.x, yv.x, fmaf(yv.y, yv.y, fmaf(yv.z, yv.z, fmaf(yv.w, yv.w, y2))));
        #pragma unroll
        for (int b = 0; b < B; b++) {
            float4 xv = xs4[b * (D / 4) + d4];   // broadcast across warp
            dot[b] = fmaf(xv.x, yv.x, dot[b]);
            dot[b] = fmaf(xv.y, yv.y, dot[b]);
            dot[b] = fmaf(xv.z, yv.z, dot[b]);
            dot[b] = fmaf(xv.w, yv.w, dot[b]);
        }
    }

    const int lane = t & 31, w = t >> 5;
    #pragma unroll
    for (int b = 0; b < B; b++) {
        float l = fmaf(sScale[b], dot[b], sA[b]) - sC[b] * y2;
        es[b * CH + t] = l;
        float m = l;
        #pragma unroll
        for (int o = 16; o > 0; o >>= 1) m = fmaxf(m, __shfl_xor_sync(0xffffffffu, m, o));
        if (lane == 0) wred[b][w] = m;
    }
    __syncthreads();
    if (t < B) {
        float m = fmaxf(fmaxf(wred[t][0], wred[t][1]), fmaxf(wred[t][2], wred[t][3]));
        cm[t] = m;
        g_cmax[t * NCH + blockIdx.x] = m;
    }
    __syncthreads();

    // exp in place
    #pragma unroll
    for (int b = 0; b < B; b++)
        es[b * CH + t] = __expf(es[b * CH + t] - cm[b]);
    __syncthreads();

    // chunk sum per b (warp w handles 8 b's)
    #pragma unroll
    for (int j = 0; j < B / 4; j++) {
        int b = w * (B / 4) + j;
        float s = es[b * CH + lane] + es[b * CH + lane + 32]
                + es[b * CH + lane + 64] + es[b * CH + lane + 96];
        #pragma unroll
        for (int o = 16; o > 0; o >>= 1) s += __shfl_xor_sync(0xffffffffu, s, o);
        if (lane == 0) g_csum[b * NCH + blockIdx.x] = s;
    }

    // ---- Phase B: acc[b][d] = sum_n e[b][n] * y[n][d], thread owns d=t ----
    float acc[B];
    #pragma unroll
    for (int b = 0; b < B; b++) acc[b] = 0.f;

    #pragma unroll 2
    for (int n4 = 0; n4 < CH / 4; n4++) {
        const int n = n4 * 4;
        float y0 = ys[(n + 0) * YSTRIDE + t];
        float y1 = ys[(n + 1) * YSTRIDE + t];
        float yv2 = ys[(n + 2) * YSTRIDE + t];
        float y3 = ys[(n + 3) * YSTRIDE + t];
        #pragma unroll
        for (int b = 0; b < B; b++) {
            float4 e = *reinterpret_cast<const float4*>(&es[b * CH + n]);  // broadcast
            acc[b] = fmaf(e.x, y0, acc[b]);
            acc[b] = fmaf(e.y, y1, acc[b]);
            acc[b] = fmaf(e.z, yv2, acc[b]);
            acc[b] = fmaf(e.w, y3, acc[b]);
        }
    }

    float* pv = g_cvec + (size_t)blockIdx.x * B * D;
    #pragma unroll
    for (int b = 0; b < B; b++) pv[b * D + t] = acc[b];
}

// ---------------------------------------------------------------------------
// K2: combine chunk partials. CTA b: M = max_c cmax, scales = exp(cmax - M),
// SE = sum scales*csum, vec = sum scales*cvec; epilogue.
// ---------------------------------------------------------------------------
__global__ __launch_bounds__(256) void k_combine(const float* __restrict__ x,
                                                 const float* __restrict__ al,
                                                 float* __restrict__ out) {
    __shared__ float sc[NCH];
    __shared__ float red[8];
    __shared__ float sM, sSE;
    __shared__ float vh[D];
    const int b = blockIdx.x, t = threadIdx.x, lane = t & 31, w = t >> 5;

    float cmv = g_cmax[b * NCH + t];
    float m = cmv;
    #pragma unroll
    for (int o = 16; o > 0; o >>= 1) m = fmaxf(m, __shfl_xor_sync(0xffffffffu, m, o));
    if (lane == 0) red[w] = m;
    __syncthreads();
    if (t < 8) {
        float mm = red[t];
        #pragma unroll
        for (int o = 4; o > 0; o >>= 1) mm = fmaxf(mm, __shfl_xor_sync(0x000000ffu, mm, o));
        if (t == 0) sM = mm;
    }
    __syncthreads();

    float s = __expf(cmv - sM);
    sc[t] = s;
    float ps = s * g_csum[b * NCH + t];
    #pragma unroll
    for (int o = 16; o > 0; o >>= 1) ps += __shfl_xor_sync(0xffffffffu, ps, o);
    if (lane == 0) red[w] = ps;
    __syncthreads();
    if (t < 8) {
        float ss = red[t];
        #pragma unroll
        for (int o = 4; o > 0; o >>= 1) ss += __shfl_xor_sync(0x000000ffu, ss, o);
        if (t == 0) sSE = ss;
    }
    __syncthreads();

    const int d = t & (D - 1);
    const int h = t >> 7;                 // half: chunks [0,128) or [128,256)
    float acc = 0.f;
    #pragma unroll 8
    for (int j = 0; j < NCH / 2; j++) {
        int c = h * (NCH / 2) + j;
        acc = fmaf(sc[c], g_cvec[((size_t)c * B + b) * D + d], acc);
    }
    if (h == 1) vh[d] = acc;
    __syncthreads();
    if (h == 0) {
        float v = acc + vh[d];
        float a = al[b];
        float var = 1.f - a;
        out[b * D + d] = (x[b * D + d] - sqrtf(a) * (v / sSE)) * rsqrtf(var);
    }
}

extern "C" void kernel_launch(void* const* d_in, const int* in_sizes, int n_in,
                              void* d_out, int out_size) {
    const float* x  = (const float*)d_in[0];   // inputs [B, D]
    const float* al = (const float*)d_in[1];   // alphas [B]
    const float* y  = (const float*)d_in[2];   // data_batch [N, D]
    float* out = (float*)d_out;                // [B, D]

    const size_t SMEM = (CH * YSTRIDE + B * D + B * CH) * sizeof(float);  // ~98 KB
    cudaFuncSetAttribute(k_chunk, cudaFuncAttributeMaxDynamicSharedMemorySize, (int)SMEM);

    k_chunk<<<NCH, 128, SMEM>>>(x, al, y);
    k_combine<<<B, 256>>>(x, al, out);
}

// round 4
// speedup vs baseline: 2.0138x; 1.2098x over previous
#include <cuda_runtime.h>
#include <math.h>

#define B 32
#define N 32768
#define D 128
#define CH 128
#define NCH (N / CH)          // 256 chunks
#define YSTRIDE (D + 4)       // 132 floats: pad to kill LDS.128 bank conflicts

// per-chunk softmax partials (no allocations allowed)
__device__ float g_cmax[B * NCH];        // [B][NCH]
__device__ float g_csum[B * NCH];        // [B][NCH]
__device__ float g_cvec[NCH * B * D];    // [NCH][B][D], 4 MB

// ---------------------------------------------------------------------------
// K1: fused chunk kernel. One CTA per 128-n chunk, 128 threads.
//  Phase A: thread t owns n=base+t; dot(x_b, y_n) for all 32 b (y,x in smem)
//           -> logits -> chunk max per b -> e = exp(l - cmax) -> chunk sum.
//  Phase B: thread t owns d=t; acc[b] = sum_n e[b][n] * y[n][d].
//  y is read from DRAM exactly once, staged in padded smem.
// ---------------------------------------------------------------------------
__global__ __launch_bounds__(128) void k_chunk(const float* __restrict__ x,
                                               const float* __restrict__ al,
                                               const float* __restrict__ y) {
    extern __shared__ float smem[];
    float* ys = smem;                    // CH * YSTRIDE   (67.6 KB)
    float* xs = ys + CH * YSTRIDE;       // B * D          (16 KB)
    float* es = xs + B * D;              // B * CH         (16 KB) logits->exp
    __shared__ float sA[B], sScale[B], sC[B], cm[B];
    __shared__ float wred[B][4];

    const int t = threadIdx.x;
    const int base = blockIdx.x * CH;

    // stage y chunk (coalesced float4, padded rows)
    const float4* y4 = reinterpret_cast<const float4*>(y + (size_t)base * D);
    #pragma unroll
    for (int i = t; i < CH * D / 4; i += 128) {
        int row = i >> 5;               // i / (D/4)
        int c4  = i & 31;
        *reinterpret_cast<float4*>(&ys[row * YSTRIDE + c4 * 4]) = y4[i];
    }
    // stage x
    const float4* x4 = reinterpret_cast<const float4*>(x);
    #pragma unroll
    for (int i = t; i < B * D / 4; i += 128)
        reinterpret_cast<float4*>(xs)[i] = x4[i];
    __syncthreads();

    if (t < B) {
        float a = al[t];
        float var = 1.0f - a;
        float x2 = 0.f;
        #pragma unroll 8
        for (int d = 0; d < D; d++) { float v = xs[t * D + d]; x2 = fmaf(v, v, x2); }
        sA[t] = -(0.5f * (float)D * logf(var) + 0.5f / var * x2);
        sScale[t] = sqrtf(a) / var;
        sC[t] = 0.5f * a / var;
    }
    __syncthreads();

    // ---- Phase A: dots + logits ----
    float dot[B];
    #pragma unroll
    for (int b = 0; b < B; b++) dot[b] = 0.f;
    float y2 = 0.f;

    const float4* yrow = reinterpret_cast<const float4*>(&ys[t * YSTRIDE]);
    const float4* xs4  = reinterpret_cast<const float4*>(xs);
    #pragma unroll 4
    for (int d4 = 0; d4 < D / 4; d4++) {
        float4 yv = yrow[d4];
        y2 = fmaf(yv.x, yv.x, fmaf(yv.y, yv.y, fmaf(yv.z, yv.z, fmaf(yv.w, yv.w, y2))));
        #pragma unroll
        for (int b = 0; b < B; b++) {
            float4 xv = xs4[b * (D / 4) + d4];   // broadcast across warp
            dot[b] = fmaf(xv.x, yv.x, dot[b]);
            dot[b] = fmaf(xv.y, yv.y, dot[b]);
            dot[b] = fmaf(xv.z, yv.z, dot[b]);
            dot[b] = fmaf(xv.w, yv.w, dot[b]);
        }
    }

    const int lane = t & 31, w = t >> 5;
    #pragma unroll
    for (int b = 0; b < B; b++) {
        float l = fmaf(sScale[b], dot[b], sA[b]) - sC[b] * y2;
        es[b * CH + t] = l;
        float m = l;
        #pragma unroll
        for (int o = 16; o > 0; o >>= 1) m = fmaxf(m, __shfl_xor_sync(0xffffffffu, m, o));
        if (lane == 0) wred[b][w] = m;
    }
    __syncthreads();
    if (t < B) {
        float m = fmaxf(fmaxf(wred[t][0], wred[t][1]), fmaxf(wred[t][2], wred[t][3]));
        cm[t] = m;
        g_cmax[t * NCH + blockIdx.x] = m;
    }
    __syncthreads();

    // exp in place
    #pragma unroll
    for (int b = 0; b < B; b++)
        es[b * CH + t] = __expf(es[b * CH + t] - cm[b]);
    __syncthreads();

    // chunk sum per b (warp w handles 8 b's)
    #pragma unroll
    for (int j = 0; j < B / 4; j++) {
        int b = w * (B / 4) + j;
        float s = es[b * CH + lane] + es[b * CH + lane + 32]
                + es[b * CH + lane + 64] + es[b * CH + lane + 96];
        #pragma unroll
        for (int o = 16; o > 0; o >>= 1) s += __shfl_xor_sync(0xffffffffu, s, o);
        if (lane == 0) g_csum[b * NCH + blockIdx.x] = s;
    }

    // ---- Phase B: acc[b][d] = sum_n e[b][n] * y[n][d], thread owns d=t ----
    float acc[B];
    #pragma unroll
    for (int b = 0; b < B; b++) acc[b] = 0.f;

    #pragma unroll 2
    for (int n4 = 0; n4 < CH / 4; n4++) {
        const int n = n4 * 4;
        float y0 = ys[(n + 0) * YSTRIDE + t];
        float y1 = ys[(n + 1) * YSTRIDE + t];
        float yv2 = ys[(n + 2) * YSTRIDE + t];
        float y3 = ys[(n + 3) * YSTRIDE + t];
        #pragma unroll
        for (int b = 0; b < B; b++) {
            float4 e = *reinterpret_cast<const float4*>(&es[b * CH + n]);  // broadcast
            acc[b] = fmaf(e.x, y0, acc[b]);
            acc[b] = fmaf(e.y, y1, acc[b]);
            acc[b] = fmaf(e.z, yv2, acc[b]);
            acc[b] = fmaf(e.w, y3, acc[b]);
        }
    }

    float* pv = g_cvec + (size_t)blockIdx.x * B * D;
    #pragma unroll
    for (int b = 0; b < B; b++) pv[b * D + t] = acc[b];
}

// ---------------------------------------------------------------------------
// K2: finisher. Grid = B * (D/4) = 1024 CTAs, 128 threads.
//  CTA (b, g): redundantly computes M_b (global max) and SE_b from the 256
//  chunk partials (block-parallel), builds sc[c] = exp(cmax-M) in smem.
//  Warp w owns output d = 4g + w; lanes stride the 256 chunks (MLP=8),
//  v = sum_c sc[c] * cvec[c][b][d]; shuffle-reduce; lane 0 epilogue.
// ---------------------------------------------------------------------------
__global__ __launch_bounds__(128) void k_final(const float* __restrict__ x,
                                               const float* __restrict__ al,
                                               float* __restrict__ out) {
    __shared__ float sc[NCH];
    __shared__ float red[4];
    __shared__ float sM, sSE;
    const int t = threadIdx.x, lane = t & 31, w = t >> 5;
    const int b = blockIdx.x >> 5;
    const int g = blockIdx.x & 31;

    // block max over 256 cmax values
    float c0 = g_cmax[b * NCH + t];
    float c1 = g_cmax[b * NCH + t + 128];
    float m = fmaxf(c0, c1);
    #pragma unroll
    for (int o = 16; o > 0; o >>= 1) m = fmaxf(m, __shfl_xor_sync(0xffffffffu, m, o));
    if (lane == 0) red[w] = m;
    __syncthreads();
    if (t == 0) sM = fmaxf(fmaxf(red[0], red[1]), fmaxf(red[2], red[3]));
    __syncthreads();
    const float M = sM;

    // scales + SE
    float s0 = __expf(c0 - M);
    float s1 = __expf(c1 - M);
    sc[t] = s0;
    sc[t + 128] = s1;
    float ps = fmaf(s0, g_csum[b * NCH + t], s1 * g_csum[b * NCH + t + 128]);
    #pragma unroll
    for (int o = 16; o > 0; o >>= 1) ps += __shfl_xor_sync(0xffffffffu, ps, o);
    if (lane == 0) red[w] = ps;
    __syncthreads();
    if (t == 0) sSE = red[0] + red[1] + red[2] + red[3];
    __syncthreads();

    // warp-per-output reduction over chunks
    const int d = g * 4 + w;
    float v = 0.f;
    #pragma unroll
    for (int j = 0; j < NCH / 32; j++) {
        const int c = j * 32 + lane;
        v = fmaf(sc[c], g_cvec[((size_t)c * B + b) * D + d], v);
    }
    #pragma unroll
    for (int o = 16; o > 0; o >>= 1) v += __shfl_xor_sync(0xffffffffu, v, o);

    if (lane == 0) {
        float a = al[b];
        float var = 1.f - a;
        out[b * D + d] = (x[b * D + d] - sqrtf(a) * (v / sSE)) * rsqrtf(var);
    }
}

extern "C" void kernel_launch(void* const* d_in, const int* in_sizes, int n_in,
                              void* d_out, int out_size) {
    const float* x  = (const float*)d_in[0];   // inputs [B, D]
    const float* al = (const float*)d_in[1];   // alphas [B]
    const float* y  = (const float*)d_in[2];   // data_batch [N, D]
    float* out = (float*)d_out;                // [B, D]

    const size_t SMEM = (CH * YSTRIDE + B * D + B * CH) * sizeof(float);  // ~98 KB
    cudaFuncSetAttribute(k_chunk, cudaFuncAttributeMaxDynamicSharedMemorySize, (int)SMEM);

    k_chunk<<<NCH, 128, SMEM>>>(x, al, y);
    k_final<<<B * (D / 4), 128>>>(x, al, out);
}